// round 5
// baseline (speedup 1.0000x reference)
#include <cuda_runtime.h>
#include <math.h>
#include <stdint.h>

#define PI_F 3.14159265358979323846f

__device__ __forceinline__ float2 cmul(float2 a, float2 b) {
    return make_float2(a.x*b.x - a.y*b.y, a.x*b.y + a.y*b.x);
}
__device__ __forceinline__ float2 cadd(float2 a, float2 b) {
    return make_float2(a.x + b.x, a.y + b.y);
}
__device__ __forceinline__ uint32_t smem_u32(const void* p) {
    return (uint32_t)__cvta_generic_to_shared(p);
}
__device__ __forceinline__ void mbar_init(uint32_t mbar, uint32_t count) {
    asm volatile("mbarrier.init.shared::cta.b64 [%0], %1;" :: "r"(mbar), "r"(count) : "memory");
}
__device__ __forceinline__ void mbar_expect_tx(uint32_t mbar, uint32_t bytes) {
    asm volatile("mbarrier.arrive.expect_tx.shared::cta.b64 _, [%0], %1;"
                 :: "r"(mbar), "r"(bytes) : "memory");
}
__device__ __forceinline__ void bulk_g2s(uint32_t dst, const void* src, uint32_t bytes, uint32_t mbar) {
    asm volatile("cp.async.bulk.shared::cta.global.mbarrier::complete_tx::bytes [%0], [%1], %2, [%3];"
                 :: "r"(dst), "l"(src), "r"(bytes), "r"(mbar) : "memory");
}
__device__ __forceinline__ void mbar_wait(uint32_t mbar, uint32_t parity) {
    asm volatile(
        "{\n\t"
        ".reg .pred P;\n\t"
        "WAIT_%=:\n\t"
        "mbarrier.try_wait.parity.acquire.cta.shared::cta.b64 P, [%0], %1, 0x989680;\n\t"
        "@P bra WAIT_DONE_%=;\n\t"
        "bra WAIT_%=;\n\t"
        "WAIT_DONE_%=:\n\t"
        "}"
        :: "r"(mbar), "r"(parity) : "memory");
}

// 128 threads, 16 rows per block (grid = B/16 = 2048).
// Phase 1: 4 chunks of 4 rows; warp w owns chunk w. Lane 0 of each warp
// issues an 8 KB cp.async.bulk into the SMEM ring; the warp waits on the
// mbarrier, then computes 4 row-dot-products from SMEM (W_enc in SMEM).
// Phase 2: threads 0..15 each simulate one row's 16-dim statevector in regs.
__global__ __launch_bounds__(128)
void qrnn_cell_kernel(const float* __restrict__ inputs,   // (B, 512)
                      const float* __restrict__ prev_h,   // (B, 4)
                      const float* __restrict__ W_enc,    // (516, 4)
                      const float* __restrict__ b_enc,    // (4,)
                      const float* __restrict__ theta,    // (2, 4, 3)
                      const float* __restrict__ W_out,    // (4, 4)
                      const float* __restrict__ b_out,    // (4,)
                      float* __restrict__ out,            // (B, 4)
                      int B)
{
    __shared__ struct {
        alignas(128) float ring[16 * 512];   // 32 KB: 4 chunks x 4 rows x 512
        float4 sW[512];                      // 8 KB: W_enc rows 0..511
        float2 sU[8][4];                     // fused U = RY*RZ*RX per (l,q)
        float  sWtail[4][4];                 // W_enc rows 512..515
        float  sWout[16];
        float  sbenc[4];
        float  sbout[4];
        float  sPre[16 * 4];
        alignas(8) unsigned long long mbar[4];
    } sm;

    const int tid  = threadIdx.x;
    const int lane = tid & 31;
    const int wid  = tid >> 5;
    const int rowbase = blockIdx.x * 16;

    // ---- mbarrier init -------------------------------------------------------
    if (tid < 4) mbar_init(smem_u32(&sm.mbar[tid]), 1);

    // ---- W_enc -> smem + batch-independent setup (pre-sync) -----------------
    const float4* w4g = reinterpret_cast<const float4*>(W_enc);
    #pragma unroll
    for (int i = 0; i < 4; i++)
        sm.sW[tid + 128 * i] = w4g[tid + 128 * i];

    if (tid < 8) {
        int l = tid >> 2, q = tid & 3;
        const float* th = theta + (l * 4 + q) * 3;
        float ca, sa, cb, sb, cy, sy;
        sincosf(0.5f * th[0], &sa, &ca);
        sincosf(0.5f * th[1], &sb, &cb);
        sincosf(0.5f * th[2], &sy, &cy);
        float2 RX0 = make_float2(ca, 0.f),  RX1 = make_float2(0.f, -sa);
        float2 RX2 = make_float2(0.f, -sa), RX3 = make_float2(ca, 0.f);
        float2 RZ0 = make_float2(cb, -sb),  RZ3 = make_float2(cb, sb);
        float2 M0 = cmul(RZ0, RX0);
        float2 M1 = cmul(RZ0, RX1);
        float2 M2 = cmul(RZ3, RX2);
        float2 M3 = cmul(RZ3, RX3);
        sm.sU[tid][0] = cadd(make_float2(cy*M0.x, cy*M0.y), make_float2(-sy*M2.x, -sy*M2.y));
        sm.sU[tid][1] = cadd(make_float2(cy*M1.x, cy*M1.y), make_float2(-sy*M3.x, -sy*M3.y));
        sm.sU[tid][2] = cadd(make_float2(sy*M0.x, sy*M0.y), make_float2( cy*M2.x,  cy*M2.y));
        sm.sU[tid][3] = cadd(make_float2(sy*M1.x, sy*M1.y), make_float2( cy*M3.x,  cy*M3.y));
    }
    if (tid >= 8 && tid < 12) {
        int r = tid - 8;
        sm.sbenc[r] = b_enc[r];
        sm.sbout[r] = b_out[r];
        #pragma unroll
        for (int j = 0; j < 4; j++)
            sm.sWtail[r][j] = W_enc[(512 + r) * 4 + j];
    }
    if (tid >= 16 && tid < 32) sm.sWout[tid - 16] = W_out[tid - 16];

    if (tid == 0)
        asm volatile("fence.proxy.async.shared::cta;" ::: "memory");
    __syncthreads();

    // ---- phase 1: bulk-load chunk + compute ---------------------------------
    {
        long r0 = (long)rowbase + 4 * wid;
        if (r0 + 4 > B) r0 = (B >= 4) ? (long)(B - 4) : 0;   // safety clamp

        uint32_t mb = smem_u32(&sm.mbar[wid]);
        if (lane == 0) {
            mbar_expect_tx(mb, 8192);
            bulk_g2s(smem_u32(&sm.ring[wid * 4 * 512]), inputs + r0 * 512, 8192, mb);
        }
        mbar_wait(mb, 0);

        const float* xs = &sm.ring[wid * 4 * 512];
        float a[4][4];
        #pragma unroll
        for (int r = 0; r < 4; r++)
            #pragma unroll
            for (int j = 0; j < 4; j++) a[r][j] = 0.f;

        #pragma unroll
        for (int t = 0; t < 16; t++) {
            float4 w = sm.sW[32 * t + lane];     // conflict-free LDS.128
            #pragma unroll
            for (int r = 0; r < 4; r++) {
                float x = xs[r * 512 + 32 * t + lane];  // conflict-free LDS.32
                a[r][0] = fmaf(x, w.x, a[r][0]);
                a[r][1] = fmaf(x, w.y, a[r][1]);
                a[r][2] = fmaf(x, w.z, a[r][2]);
                a[r][3] = fmaf(x, w.w, a[r][3]);
            }
        }

        // 6-shuffle reduction per row: every lane ends with S_{lane&3}
        bool p1b = lane & 1, p2b = lane & 2;
        #pragma unroll
        for (int r = 0; r < 4; r++) {
            float v01 = p1b ? a[r][1] : a[r][0], o01 = p1b ? a[r][0] : a[r][1];
            v01 += __shfl_xor_sync(0xffffffffu, o01, 1);
            float v23 = p1b ? a[r][3] : a[r][2], o23 = p1b ? a[r][2] : a[r][3];
            v23 += __shfl_xor_sync(0xffffffffu, o23, 1);
            float v = p2b ? v23 : v01, o = p2b ? v01 : v23;
            v += __shfl_xor_sync(0xffffffffu, o, 2);
            v += __shfl_xor_sync(0xffffffffu, v, 4);
            v += __shfl_xor_sync(0xffffffffu, v, 8);
            v += __shfl_xor_sync(0xffffffffu, v, 16);
            if (lane < 4) sm.sPre[(4 * wid + r) * 4 + lane] = v;
        }
    }
    __syncthreads();

    // ---------------- phase 2: per-row quantum circuit in registers ----------
    if (tid < 16) {
        int row = rowbase + tid;
        if (row < B) {
            float4 ph = reinterpret_cast<const float4*>(prev_h)[row];
            float acc[4];
            #pragma unroll
            for (int j = 0; j < 4; j++) {
                acc[j] = sm.sPre[tid * 4 + j] + sm.sbenc[j]
                       + ph.x * sm.sWtail[0][j] + ph.y * sm.sWtail[1][j]
                       + ph.z * sm.sWtail[2][j] + ph.w * sm.sWtail[3][j];
            }
            float cv[4], sv[4];
            #pragma unroll
            for (int q = 0; q < 4; q++) {
                float half = tanhf(acc[q]) * (0.5f * PI_F);
                __sincosf(half, &sv[q], &cv[q]);
            }
            // product state (real)
            float sr[16], si[16];
            #pragma unroll
            for (int i = 0; i < 16; i++) {
                float v = ((i & 8) ? sv[0] : cv[0])
                        * ((i & 4) ? sv[1] : cv[1])
                        * ((i & 2) ? sv[2] : cv[2])
                        * ((i & 1) ? sv[3] : cv[3]);
                sr[i] = v;
                si[i] = 0.f;
            }
            // L=2 layers: fused 1q gate per qubit, then CNOT chain
            #pragma unroll
            for (int l = 0; l < 2; l++) {
                #pragma unroll
                for (int q = 0; q < 4; q++) {
                    float2 u00 = sm.sU[l*4+q][0];
                    float2 u01 = sm.sU[l*4+q][1];
                    float2 u10 = sm.sU[l*4+q][2];
                    float2 u11 = sm.sU[l*4+q][3];
                    const int m = 8 >> q;
                    #pragma unroll
                    for (int i = 0; i < 16; i++) {
                        if (i & m) continue;
                        const int i1 = i | m;
                        float ar = sr[i],  ai = si[i];
                        float br = sr[i1], bi = si[i1];
                        sr[i]  = u00.x*ar - u00.y*ai + u01.x*br - u01.y*bi;
                        si[i]  = u00.x*ai + u00.y*ar + u01.x*bi + u01.y*br;
                        sr[i1] = u10.x*ar - u10.y*ai + u11.x*br - u11.y*bi;
                        si[i1] = u10.x*ai + u10.y*ar + u11.x*bi + u11.y*br;
                    }
                }
                #pragma unroll
                for (int q = 0; q < 3; q++) {
                    const int mc = 8 >> q, mt = 4 >> q;
                    #pragma unroll
                    for (int i = 0; i < 16; i++) {
                        if ((i & mc) && !(i & mt)) {
                            const int i1 = i | mt;
                            float tr = sr[i]; sr[i] = sr[i1]; sr[i1] = tr;
                            float ti = si[i]; si[i] = si[i1]; si[i1] = ti;
                        }
                    }
                }
            }
            // PauliZ expectations
            float ev[4] = {0.f, 0.f, 0.f, 0.f};
            #pragma unroll
            for (int i = 0; i < 16; i++) {
                float p = sr[i]*sr[i] + si[i]*si[i];
                ev[0] += (i & 8) ? -p : p;
                ev[1] += (i & 4) ? -p : p;
                ev[2] += (i & 2) ? -p : p;
                ev[3] += (i & 1) ? -p : p;
            }
            float4 o;
            o.x = tanhf(ev[0]*sm.sWout[0] + ev[1]*sm.sWout[4] + ev[2]*sm.sWout[8]  + ev[3]*sm.sWout[12] + sm.sbout[0]);
            o.y = tanhf(ev[0]*sm.sWout[1] + ev[1]*sm.sWout[5] + ev[2]*sm.sWout[9]  + ev[3]*sm.sWout[13] + sm.sbout[1]);
            o.z = tanhf(ev[0]*sm.sWout[2] + ev[1]*sm.sWout[6] + ev[2]*sm.sWout[10] + ev[3]*sm.sWout[14] + sm.sbout[2]);
            o.w = tanhf(ev[0]*sm.sWout[3] + ev[1]*sm.sWout[7] + ev[2]*sm.sWout[11] + ev[3]*sm.sWout[15] + sm.sbout[3]);
            reinterpret_cast<float4*>(out)[row] = o;
        }
    }
}

extern "C" void kernel_launch(void* const* d_in, const int* in_sizes, int n_in,
                              void* d_out, int out_size)
{
    const float* inputs = (const float*)d_in[0];
    const float* prev_h = (const float*)d_in[1];
    const float* W_enc  = (const float*)d_in[2];
    const float* b_enc  = (const float*)d_in[3];
    const float* theta  = (const float*)d_in[4];
    const float* W_out  = (const float*)d_in[5];
    const float* b_out  = (const float*)d_in[6];

    int B = in_sizes[0] / 512;
    int grid = (B + 15) / 16;
    qrnn_cell_kernel<<<grid, 128>>>(inputs, prev_h, W_enc, b_enc, theta,
                                    W_out, b_out, (float*)d_out, B);
}

// round 6
// speedup vs baseline: 1.1326x; 1.1326x over previous
#include <cuda_runtime.h>
#include <math.h>
#include <stdint.h>

#define PI_F 3.14159265358979323846f

__device__ __forceinline__ float2 cmul(float2 a, float2 b) {
    return make_float2(a.x*b.x - a.y*b.y, a.x*b.y + a.y*b.x);
}
__device__ __forceinline__ float2 cadd(float2 a, float2 b) {
    return make_float2(a.x + b.x, a.y + b.y);
}
__device__ __forceinline__ uint32_t smem_u32(const void* p) {
    return (uint32_t)__cvta_generic_to_shared(p);
}
__device__ __forceinline__ void mbar_init(uint32_t mbar, uint32_t count) {
    asm volatile("mbarrier.init.shared::cta.b64 [%0], %1;" :: "r"(mbar), "r"(count) : "memory");
}
__device__ __forceinline__ void mbar_expect_tx(uint32_t mbar, uint32_t bytes) {
    asm volatile("mbarrier.arrive.expect_tx.shared::cta.b64 _, [%0], %1;"
                 :: "r"(mbar), "r"(bytes) : "memory");
}
__device__ __forceinline__ void bulk_g2s(uint32_t dst, const void* src, uint32_t bytes, uint32_t mbar) {
    asm volatile("cp.async.bulk.shared::cta.global.mbarrier::complete_tx::bytes [%0], [%1], %2, [%3];"
                 :: "r"(dst), "l"(src), "r"(bytes), "r"(mbar) : "memory");
}
__device__ __forceinline__ void mbar_wait(uint32_t mbar, uint32_t parity) {
    asm volatile(
        "{\n\t"
        ".reg .pred P;\n\t"
        "WAIT_%=:\n\t"
        "mbarrier.try_wait.parity.acquire.cta.shared::cta.b64 P, [%0], %1, 0x989680;\n\t"
        "@P bra WAIT_DONE_%=;\n\t"
        "bra WAIT_%=;\n\t"
        "WAIT_DONE_%=:\n\t"
        "}"
        :: "r"(mbar), "r"(parity) : "memory");
}

// Chunk = 4 rows (8 KB). Each warp owns CPW contiguous chunks with a private
// 3-slot ring: prologue fills 3 slots, then wait/compute/refill. Accs are
// parked in smem; after all chunks, lanes 0..4*nc-1 each run one row's
// quantum circuit (lane-efficient phase 2).
struct SMLayout {
    alignas(128) float ring[4][3][4 * 512];  // 96 KB: warp x slot x 8KB
    float4 sW[512];                          //  8 KB
    float2 sU[8][4];
    float  sWtail[4][4];
    float  sWout[16];
    float  sbenc[4];
    float  sbout[4];
    float  sAcc[4][28][5];                   // padded stride 5: conflict-free
    alignas(8) unsigned long long mbar[4][3];
};

__global__ __launch_bounds__(128)
void qrnn_cell_kernel(const float* __restrict__ inputs,   // (B, 512)
                      const float* __restrict__ prev_h,   // (B, 4)
                      const float* __restrict__ W_enc,    // (516, 4)
                      const float* __restrict__ b_enc,    // (4,)
                      const float* __restrict__ theta,    // (2, 4, 3)
                      const float* __restrict__ W_out,    // (4, 4)
                      const float* __restrict__ b_out,    // (4,)
                      float* __restrict__ out,            // (B, 4)
                      int B)
{
    extern __shared__ unsigned char smraw[];
    SMLayout* sm = reinterpret_cast<SMLayout*>(smraw);

    const int tid  = threadIdx.x;
    const int lane = tid & 31;
    const int wid  = tid >> 5;

    // ---- warp work assignment (contiguous chunks) ---------------------------
    const int chunks = (B + 3) >> 2;                       // 4-row chunks
    const int warps_total = gridDim.x * 4;
    const int cpw = (chunks + warps_total - 1) / warps_total;   // == 7 here
    const int wstart = (blockIdx.x * 4 + wid) * cpw;
    int nc = chunks - wstart;
    if (nc < 0) nc = 0;
    if (nc > cpw) nc = cpw;

    // ---- per-warp mbarrier init + prologue loads (before any block sync) ----
    if (lane == 0) {
        #pragma unroll
        for (int j = 0; j < 3; j++)
            mbar_init(smem_u32(&sm->mbar[wid][j]), 1);
        asm volatile("fence.proxy.async.shared::cta;" ::: "memory");
        #pragma unroll
        for (int j = 0; j < 3; j++) {
            if (j < nc) {
                long r0 = (long)(wstart + j) * 4;
                if (r0 + 4 > B) r0 = B - 4;                // assumes B >= 4
                uint32_t mb = smem_u32(&sm->mbar[wid][j]);
                mbar_expect_tx(mb, 8192);
                bulk_g2s(smem_u32(&sm->ring[wid][j][0]), inputs + r0 * 512, 8192, mb);
            }
        }
    }

    // ---- prefetch prev_h for this warp's rows (consumed at the very end) ----
    float4 ph = make_float4(0.f, 0.f, 0.f, 0.f);
    {
        long prow = (long)wstart * 4 + lane;
        if (lane < 4 * nc && prow < B)
            ph = reinterpret_cast<const float4*>(prev_h)[prow];
    }

    // ---- W_enc -> smem + batch-independent setup ----------------------------
    const float4* w4g = reinterpret_cast<const float4*>(W_enc);
    #pragma unroll
    for (int i = 0; i < 4; i++)
        sm->sW[tid + 128 * i] = w4g[tid + 128 * i];

    if (tid < 8) {
        int l = tid >> 2, q = tid & 3;
        const float* th = theta + (l * 4 + q) * 3;
        float ca, sa, cb, sb, cy, sy;
        sincosf(0.5f * th[0], &sa, &ca);
        sincosf(0.5f * th[1], &sb, &cb);
        sincosf(0.5f * th[2], &sy, &cy);
        float2 RX0 = make_float2(ca, 0.f),  RX1 = make_float2(0.f, -sa);
        float2 RX2 = make_float2(0.f, -sa), RX3 = make_float2(ca, 0.f);
        float2 RZ0 = make_float2(cb, -sb),  RZ3 = make_float2(cb, sb);
        float2 M0 = cmul(RZ0, RX0);
        float2 M1 = cmul(RZ0, RX1);
        float2 M2 = cmul(RZ3, RX2);
        float2 M3 = cmul(RZ3, RX3);
        sm->sU[tid][0] = cadd(make_float2(cy*M0.x, cy*M0.y), make_float2(-sy*M2.x, -sy*M2.y));
        sm->sU[tid][1] = cadd(make_float2(cy*M1.x, cy*M1.y), make_float2(-sy*M3.x, -sy*M3.y));
        sm->sU[tid][2] = cadd(make_float2(sy*M0.x, sy*M0.y), make_float2( cy*M2.x,  cy*M2.y));
        sm->sU[tid][3] = cadd(make_float2(sy*M1.x, sy*M1.y), make_float2( cy*M3.x,  cy*M3.y));
    }
    if (tid >= 8 && tid < 12) {
        int r = tid - 8;
        sm->sbenc[r] = b_enc[r];
        sm->sbout[r] = b_out[r];
        #pragma unroll
        for (int j = 0; j < 4; j++)
            sm->sWtail[r][j] = W_enc[(512 + r) * 4 + j];
    }
    if (tid >= 16 && tid < 32) sm->sWout[tid - 16] = W_out[tid - 16];
    __syncthreads();   // sW/sU/etc visible to all warps; ring is per-warp private

    // ---- phase 1 pipeline: wait slot -> compute -> refill slot --------------
    const bool p1b = lane & 1, p2b = lane & 2;
    int par = 0;
    for (int base = 0; base < nc; base += 3) {
        #pragma unroll
        for (int j = 0; j < 3; j++) {
            const int i = base + j;
            if (i >= nc) break;

            mbar_wait(smem_u32(&sm->mbar[wid][j]), par);

            const float* xs = &sm->ring[wid][j][0];
            float a[4][4];
            #pragma unroll
            for (int r = 0; r < 4; r++)
                #pragma unroll
                for (int c = 0; c < 4; c++) a[r][c] = 0.f;

            #pragma unroll
            for (int t = 0; t < 16; t++) {
                float4 w = sm->sW[32 * t + lane];          // LDS.128 conflict-free
                #pragma unroll
                for (int r = 0; r < 4; r++) {
                    float x = xs[r * 512 + 32 * t + lane]; // LDS.32 conflict-free
                    a[r][0] = fmaf(x, w.x, a[r][0]);
                    a[r][1] = fmaf(x, w.y, a[r][1]);
                    a[r][2] = fmaf(x, w.z, a[r][2]);
                    a[r][3] = fmaf(x, w.w, a[r][3]);
                }
            }
            // 6-shuffle reduction per row: every lane ends with S_{lane&3}
            #pragma unroll
            for (int r = 0; r < 4; r++) {
                float v01 = p1b ? a[r][1] : a[r][0], o01 = p1b ? a[r][0] : a[r][1];
                v01 += __shfl_xor_sync(0xffffffffu, o01, 1);
                float v23 = p1b ? a[r][3] : a[r][2], o23 = p1b ? a[r][2] : a[r][3];
                v23 += __shfl_xor_sync(0xffffffffu, o23, 1);
                float v = p2b ? v23 : v01, o = p2b ? v01 : v23;
                v += __shfl_xor_sync(0xffffffffu, o, 2);
                v += __shfl_xor_sync(0xffffffffu, v, 4);
                v += __shfl_xor_sync(0xffffffffu, v, 8);
                v += __shfl_xor_sync(0xffffffffu, v, 16);
                if (lane < 4) sm->sAcc[wid][i * 4 + r][lane] = v;
            }

            __syncwarp();                     // all lanes done reading slot j
            const int nxt = i + 3;
            if (nxt < nc && lane == 0) {      // refill slot j with chunk i+3
                long r0 = (long)(wstart + nxt) * 4;
                if (r0 + 4 > B) r0 = B - 4;
                uint32_t mb = smem_u32(&sm->mbar[wid][j]);
                mbar_expect_tx(mb, 8192);
                bulk_g2s(smem_u32(&sm->ring[wid][j][0]), inputs + r0 * 512, 8192, mb);
            }
        }
        par ^= 1;
    }
    __syncwarp();

    // ---- phase 2: one circuit per lane (lanes 0..4*nc-1) --------------------
    if (lane < 4 * nc) {
        long row = (long)wstart * 4 + lane;
        if (row < B) {
            float acc[4];
            #pragma unroll
            for (int jj = 0; jj < 4; jj++) {
                acc[jj] = sm->sAcc[wid][lane][jj] + sm->sbenc[jj]
                        + ph.x * sm->sWtail[0][jj] + ph.y * sm->sWtail[1][jj]
                        + ph.z * sm->sWtail[2][jj] + ph.w * sm->sWtail[3][jj];
            }
            float cv[4], sv[4];
            #pragma unroll
            for (int q = 0; q < 4; q++) {
                float half = tanhf(acc[q]) * (0.5f * PI_F);
                __sincosf(half, &sv[q], &cv[q]);
            }
            float sr[16], si[16];
            #pragma unroll
            for (int i = 0; i < 16; i++) {
                float v = ((i & 8) ? sv[0] : cv[0])
                        * ((i & 4) ? sv[1] : cv[1])
                        * ((i & 2) ? sv[2] : cv[2])
                        * ((i & 1) ? sv[3] : cv[3]);
                sr[i] = v;
                si[i] = 0.f;
            }
            #pragma unroll
            for (int l = 0; l < 2; l++) {
                #pragma unroll
                for (int q = 0; q < 4; q++) {
                    float2 u00 = sm->sU[l*4+q][0];
                    float2 u01 = sm->sU[l*4+q][1];
                    float2 u10 = sm->sU[l*4+q][2];
                    float2 u11 = sm->sU[l*4+q][3];
                    const int m = 8 >> q;
                    #pragma unroll
                    for (int i = 0; i < 16; i++) {
                        if (i & m) continue;
                        const int i1 = i | m;
                        float ar = sr[i],  ai = si[i];
                        float br = sr[i1], bi = si[i1];
                        sr[i]  = u00.x*ar - u00.y*ai + u01.x*br - u01.y*bi;
                        si[i]  = u00.x*ai + u00.y*ar + u01.x*bi + u01.y*br;
                        sr[i1] = u10.x*ar - u10.y*ai + u11.x*br - u11.y*bi;
                        si[i1] = u10.x*ai + u10.y*ar + u11.x*bi + u11.y*br;
                    }
                }
                #pragma unroll
                for (int q = 0; q < 3; q++) {
                    const int mc = 8 >> q, mt = 4 >> q;
                    #pragma unroll
                    for (int i = 0; i < 16; i++) {
                        if ((i & mc) && !(i & mt)) {
                            const int i1 = i | mt;
                            float tr = sr[i]; sr[i] = sr[i1]; sr[i1] = tr;
                            float ti = si[i]; si[i] = si[i1]; si[i1] = ti;
                        }
                    }
                }
            }
            float ev[4] = {0.f, 0.f, 0.f, 0.f};
            #pragma unroll
            for (int i = 0; i < 16; i++) {
                float p = sr[i]*sr[i] + si[i]*si[i];
                ev[0] += (i & 8) ? -p : p;
                ev[1] += (i & 4) ? -p : p;
                ev[2] += (i & 2) ? -p : p;
                ev[3] += (i & 1) ? -p : p;
            }
            float4 o;
            o.x = tanhf(ev[0]*sm->sWout[0] + ev[1]*sm->sWout[4] + ev[2]*sm->sWout[8]  + ev[3]*sm->sWout[12] + sm->sbout[0]);
            o.y = tanhf(ev[0]*sm->sWout[1] + ev[1]*sm->sWout[5] + ev[2]*sm->sWout[9]  + ev[3]*sm->sWout[13] + sm->sbout[1]);
            o.z = tanhf(ev[0]*sm->sWout[2] + ev[1]*sm->sWout[6] + ev[2]*sm->sWout[10] + ev[3]*sm->sWout[14] + sm->sbout[2]);
            o.w = tanhf(ev[0]*sm->sWout[3] + ev[1]*sm->sWout[7] + ev[2]*sm->sWout[11] + ev[3]*sm->sWout[15] + sm->sbout[3]);
            reinterpret_cast<float4*>(out)[row] = o;
        }
    }
}

extern "C" void kernel_launch(void* const* d_in, const int* in_sizes, int n_in,
                              void* d_out, int out_size)
{
    const float* inputs = (const float*)d_in[0];
    const float* prev_h = (const float*)d_in[1];
    const float* W_enc  = (const float*)d_in[2];
    const float* b_enc  = (const float*)d_in[3];
    const float* theta  = (const float*)d_in[4];
    const float* W_out  = (const float*)d_in[5];
    const float* b_out  = (const float*)d_in[6];

    int B = in_sizes[0] / 512;
    const int smem_bytes = (int)sizeof(SMLayout);
    cudaFuncSetAttribute(qrnn_cell_kernel,
                         cudaFuncAttributeMaxDynamicSharedMemorySize, smem_bytes);

    int grid = 296;   // 2 blocks/SM on 148 SMs, single wave, persistent warps
    qrnn_cell_kernel<<<grid, 128, smem_bytes>>>(inputs, prev_h, W_enc, b_enc, theta,
                                                W_out, b_out, (float*)d_out, B);
}